// round 13
// baseline (speedup 1.0000x reference)
#include <cuda_runtime.h>
#include <math.h>

// ---------------------------------------------------------------------------
// KANConvNet round 12: parity-split phi layout. All convs are stride-2, so
// column parity of a tap is block-uniform (kw&1). Each phi pair-plane is split
// into even/odd column arrays -> warp loads become fully coalesced
// (2 wavefronts per LDG.64 instead of 4).
//   phi layout: [5 pairs][2 parities][B*C*HPd*WPH], WPH = WPd/2 (rounded up).
//   Conv f-loop reordered per (c,kh) row: even kw taps, then odd kw taps;
//   SMEM weight tile packed in matching order.
// ---------------------------------------------------------------------------

// L0 input: 8x3x224x224, pad 3 -> 230x230, WPH=115
#define HP0 230
#define WPH0 115
#define NPIXH0 (8 * 3 * HP0 * WPH0)
// L1 input: pooled 56x56, pad 1 -> 58x58, WPH=29
#define HP1 58
#define WPH1 29
#define NPIXH1 (8 * 16 * HP1 * WPH1)
// L2 input: pooled 14x14, pad 1 -> 16x16, WPH=8
#define HP2 16
#define WPH2 8
#define NPIXH2 (8 * 32 * HP2 * WPH2)

__device__ float g_wp0[147 * 9 * 16];
__device__ float g_wp1[144 * 9 * 32];
__device__ float g_wp2[288 * 9 * 64];
__device__ float g_wpc[64  * 9 * 200];

__device__ float2 g_phi0[10 * NPIXH0];
__device__ float  g_part0[3 * 8 * 16 * 112 * 112];
__device__ float2 g_phi1[10 * NPIXH1];
__device__ float  g_part1[16 * 8 * 32 * 28 * 28];
__device__ float2 g_phi2[10 * NPIXH2];
__device__ float  g_part2[32 * 8 * 64 * 7 * 7];
__device__ float  g_a2[8 * 64 * 7 * 7];

#define N0P (147 * 9 * 16)
#define N1P (144 * 9 * 32)
#define N2P (288 * 9 * 64)
#define NCP (64  * 9 * 200)

// ---------------- packed f32x2 helpers ----------------
__device__ __forceinline__ long long pk2(float a) {
    long long r;
    asm("mov.b64 %0, {%1, %1};" : "=l"(r) : "f"(a));
    return r;
}
__device__ __forceinline__ long long ffma2(long long a, long long b, long long c) {
    long long d;
    asm("fma.rn.f32x2 %0, %1, %2, %3;" : "=l"(d) : "l"(a), "l"(b), "l"(c));
    return d;
}
__device__ __forceinline__ float2 upk2(long long a) {
    float x, y;
    asm("mov.b64 {%0, %1}, %2;" : "=f"(x), "=f"(y) : "l"(a));
    return make_float2(x, y);
}

// ---------------- dense 9-coefficient evaluation ----------------
__device__ __forceinline__ void eval9(float x, float* c) {
    float sig = 1.0f / (1.0f + __expf(-x));
    c[0] = x * sig;
    float t  = fmaf(x, 2.5f, 5.5f);          // (x + 2.2) / 0.4
    float mf = floorf(t);
    bool inr = (mf >= 0.0f) && (mf <= 10.0f);
    mf = fminf(fmaxf(mf, 0.0f), 10.0f);
    float u  = t - mf;
    float u2 = u * u;
    float u3 = u2 * u;
    float om = 1.0f - u;
    const float s6 = 1.0f / 6.0f;
    float w0 = s6 * om * om * om;
    float w1 = s6 * fmaf(3.0f, u3, fmaf(-6.0f, u2, 4.0f));
    float w2 = s6 * fmaf(-3.0f, u3, fmaf(3.0f, u2, fmaf(3.0f, u, 1.0f)));
    float w3 = s6 * u3;
    int m = (int)mf;
#pragma unroll
    for (int r = 1; r < 9; r++) {
        int tt = (r - 1) - (m - 3);
        float cv = 0.0f;
        cv = (tt == 0) ? w0 : cv;
        cv = (tt == 1) ? w1 : cv;
        cv = (tt == 2) ? w2 : cv;
        cv = (tt == 3) ? w3 : cv;
        c[r] = inr ? cv : 0.0f;
    }
}

// eval5 (sparse) for the classifier head
__device__ __forceinline__ void eval5(float x, float& c0, float* w, int* r) {
    float sig = 1.0f / (1.0f + __expf(-x));
    c0 = x * sig;
    float t  = fmaf(x, 2.5f, 5.5f);
    float mf = floorf(t);
    bool inr = (mf >= 0.0f) && (mf <= 10.0f);
    mf = fminf(fmaxf(mf, 0.0f), 10.0f);
    float u  = t - mf;
    float u2 = u * u;
    float u3 = u2 * u;
    float om = 1.0f - u;
    const float s6 = 1.0f / 6.0f;
    float a0 = s6 * om * om * om;
    float a1 = s6 * fmaf(3.0f, u3, fmaf(-6.0f, u2, 4.0f));
    float a2 = s6 * fmaf(-3.0f, u3, fmaf(3.0f, u2, fmaf(3.0f, u, 1.0f)));
    float a3 = s6 * u3;
    int m = (int)mf;
    w[0] = (inr && m >= 3)            ? a0 : 0.0f;
    w[1] = (inr && m >= 2 && m <= 9)  ? a1 : 0.0f;
    w[2] = (inr && m >= 1 && m <= 8)  ? a2 : 0.0f;
    w[3] = (inr && m <= 7)            ? a3 : 0.0f;
#pragma unroll
    for (int t4 = 0; t4 < 4; t4++) {
        int j = m - 3 + t4;
        j = j < 0 ? 0 : (j > 7 ? 7 : j);
        r[t4] = 1 + j;
    }
}

// store 9 coefficients into parity-split planes
__device__ __forceinline__ void store_phi_par(float2* __restrict__ phi,
                                              long long n, int par, long long i,
                                              const float* c) {
    phi[(0 * 2 + par) * n + i] = make_float2(c[0], c[1]);
    phi[(1 * 2 + par) * n + i] = make_float2(c[2], c[3]);
    phi[(2 * 2 + par) * n + i] = make_float2(c[4], c[5]);
    phi[(3 * 2 + par) * n + i] = make_float2(c[6], c[7]);
    phi[(4 * 2 + par) * n + i] = make_float2(c[8], 0.0f);
}

// ---------------- phi precompute into PADDED parity layout (layer-0) -------
__global__ void phi_eval_pad(const float* __restrict__ x, float2* __restrict__ phi,
                             int B, int C, int H, int W, int P,
                             int WPH, int npixh) {
    int WPd = W + 2 * P, HPd = H + 2 * P;
    int ncell = B * C * HPd * WPd;
    int i = blockIdx.x * blockDim.x + threadIdx.x;
    if (i >= ncell) return;
    int wp_ = i % WPd;
    int t   = i / WPd;
    int hp_ = t % HPd;
    t /= HPd;
    int c = t % C;
    int b = t / C;
    int hin = hp_ - P, win = wp_ - P;
    float xv = 0.0f;
    if (hin >= 0 && hin < H && win >= 0 && win < W)
        xv = x[((b * C + c) * H + hin) * W + win];
    float cf[9];
    eval9(xv, cf);
    long long idxH = ((long long)(b * C + c) * HPd + hp_) * WPH + (wp_ >> 1);
    store_phi_par(phi, npixh, wp_ & 1, idxH, cf);
}

// ---------------- merged weight packing ----------------
__device__ __forceinline__ void pack_one(int idx,
                                         const float* __restrict__ bw,
                                         const float* __restrict__ sw,
                                         const float* __restrict__ sc,
                                         float* __restrict__ wp,
                                         int OUT, int IN) {
    int i   = idx / (9 * OUT);
    int rem = idx - i * 9 * OUT;
    int r   = rem / OUT;
    int o   = rem - r * OUT;
    int oi  = o * IN + i;
    float v = (r == 0) ? bw[oi] : sw[oi * 8 + (r - 1)] * sc[oi];
    wp[idx] = v;
}

__global__ void pack_all(const float* bw0, const float* sw0, const float* sc0,
                         const float* bw1, const float* sw1, const float* sc1,
                         const float* bw2, const float* sw2, const float* sc2,
                         const float* bwc, const float* swc, const float* scc,
                         float* wp0, float* wp1, float* wp2, float* wpc) {
    int idx = blockIdx.x * blockDim.x + threadIdx.x;
    if (idx < N0P) { pack_one(idx, bw0, sw0, sc0, wp0, 16, 147); return; }
    idx -= N0P;
    if (idx < N1P) { pack_one(idx, bw1, sw1, sc1, wp1, 32, 144); return; }
    idx -= N1P;
    if (idx < N2P) { pack_one(idx, bw2, sw2, sc2, wp2, 64, 288); return; }
    idx -= N2P;
    if (idx < NCP) { pack_one(idx, bwc, swc, scc, wpc, 200, 64); }
}

// 16-output FMA step: wr -> [9][16] weight rows in smem, cr -> 5 float2s.
__device__ __forceinline__ void fmastep16(const float* wr, const float2* cr,
                                          long long* acc) {
#pragma unroll
    for (int r = 0; r < 9; r++) {
        const ulonglong2* wv = (const ulonglong2*)(wr + r * 16);
        float cf = (r & 1) ? cr[r >> 1].y : cr[r >> 1].x;
        long long cp = pk2(cf);
#pragma unroll
        for (int q = 0; q < 4; q++) {
            ulonglong2 a = wv[q];
            acc[2 * q]     = ffma2(cp, (long long)a.x, acc[2 * q]);
            acc[2 * q + 1] = ffma2(cp, (long long)a.y, acc[2 * q + 1]);
        }
    }
}

// ---------------------------------------------------------------------------
// Dense gather-GEMM conv over parity-split padded phi. CSL channels/slice,
// K*K taps each; per (c,kh) row: even-kw taps then odd-kw taps.
// ---------------------------------------------------------------------------
template <int CIN, int K, int OUT, int OT, int PX, int T, int CSL>
__global__ void __launch_bounds__(T, 3)
kan_conv_g(const float2* __restrict__ phi,  // [5][2][B*CIN*HPd*WPH]
           const float* __restrict__ wp,    // [F][9][OUT]
           float* __restrict__ out,
           int B, int HPd, int WPH, int Ho, int Wo) {
    const int NE  = (K + 1) / 2;
    const int FSL = CSL * K * K;
    __shared__ float swm[CSL * K * K * 9 * OT];
    const int NOT    = OUT / OT;
    const int sl     = blockIdx.y / NOT;
    const int ot     = blockIdx.y - sl * NOT;
    const int NPIXH  = B * CIN * HPd * WPH;

    // SMEM weight tile in tap order [cl][kh][evens..., odds...]
    for (int idx = threadIdx.x; idx < FSL * 9 * OT; idx += T) {
        int o  = idx % OT;
        int t  = idx / OT;
        int r  = t % 9;  t /= 9;
        int pos = t % K; t /= K;
        int kh = t % K;
        int cl = t / K;
        int kw = (pos < NE) ? 2 * pos : 2 * (pos - NE) + 1;
        int f  = (sl * CSL + cl) * K * K + kh * K + kw;
        swm[idx] = wp[(f * 9 + r) * OUT + ot * OT + o];
    }
    __syncthreads();

    const float2* plA[5];
    const float2* plB[5];
#pragma unroll
    for (int r = 0; r < 5; r++) {
        plA[r] = phi + (long long)(2 * r) * NPIXH;
        plB[r] = phi + (long long)(2 * r + 1) * NPIXH;
    }

    const int N = B * Ho * Wo;
    int  off[PX];
    bool pv[PX];
#pragma unroll
    for (int p = 0; p < PX; p++) {
        int gp = blockIdx.x * T * PX + p * T + threadIdx.x;
        pv[p]  = gp < N;
        int g  = pv[p] ? gp : 0;
        int b  = g / (Ho * Wo);
        int rr = g - b * Ho * Wo;
        int ho = rr / Wo;
        int wo = rr - ho * Wo;
        off[p] = (b * CIN * HPd + ho * 2) * WPH + wo;   // stride-2, half-index
    }

    long long acc[PX][OT / 2];
#pragma unroll
    for (int p = 0; p < PX; p++)
#pragma unroll
        for (int k = 0; k < OT / 2; k++) acc[p][k] = 0LL;

    const float* wr = swm;
#pragma unroll 1
    for (int cl = 0; cl < CSL; cl++) {
        int c = sl * CSL + cl;
#pragma unroll 1
        for (int kh = 0; kh < K; kh++) {
            int vofs = (c * HPd + kh) * WPH;
            // even-kw taps (parity 0), half-offset j = kw/2
#pragma unroll 1
            for (int j = 0; j < NE; j++) {
                float2 cr[PX][5];
#pragma unroll
                for (int p = 0; p < PX; p++) {
                    int idx = off[p] + vofs + j;
#pragma unroll
                    for (int r = 0; r < 5; r++)
                        cr[p][r] = __ldg(plA[r] + idx);
                }
#pragma unroll
                for (int p = 0; p < PX; p++)
                    fmastep16(wr, cr[p], acc[p]);
                wr += 9 * OT;
            }
            // odd-kw taps (parity 1), half-offset j = (kw-1)/2
#pragma unroll 1
            for (int j = 0; j < K - NE; j++) {
                float2 cr[PX][5];
#pragma unroll
                for (int p = 0; p < PX; p++) {
                    int idx = off[p] + vofs + j;
#pragma unroll
                    for (int r = 0; r < 5; r++)
                        cr[p][r] = __ldg(plB[r] + idx);
                }
#pragma unroll
                for (int p = 0; p < PX; p++)
                    fmastep16(wr, cr[p], acc[p]);
                wr += 9 * OT;
            }
        }
    }

    long long HW = (long long)Ho * Wo;
    float* ob = out + (long long)sl * B * OUT * HW;
#pragma unroll
    for (int p = 0; p < PX; p++) {
        if (!pv[p]) continue;
        int gp = blockIdx.x * T * PX + p * T + threadIdx.x;
        int b  = gp / (Ho * Wo);
        int rr = gp - b * Ho * Wo;
        float* op = ob + (long long)(b * OUT + ot * OT) * HW + rr;
#pragma unroll
        for (int k = 0; k < OT / 2; k++) {
            float2 v = upk2(acc[p][k]);
            op[(2 * k) * HW]     = v.x;
            op[(2 * k + 1) * HW] = v.y;
        }
    }
}

// ---------------------------------------------------------------------------
// sum NP partials -> relu -> 2x2 max pool -> phi into parity-split padded layout
// ---------------------------------------------------------------------------
template <int NP>
__global__ void maxpool_sum_phi_pad(const float* __restrict__ in,  // partials (B,C,H,W)
                                    float2* __restrict__ phi,
                                    int B, int C, int H, int W,    // pre-pool dims
                                    int P, int WPH, int npixh) {
    int Ho = H / 2, Wo = W / 2;
    int WPd = Wo + 2 * P, HPd = Ho + 2 * P;
    int ncell = B * C * HPd * WPd;
    long long sz = (long long)B * C * H * W;
    int i = blockIdx.x * blockDim.x + threadIdx.x;
    if (i >= ncell) return;
    int wp_ = i % WPd;
    int t   = i / WPd;
    int hp_ = t % HPd;
    t /= HPd;
    int c = t % C;
    int b = t / C;
    int ho = hp_ - P, wo = wp_ - P;
    float m = 0.0f;
    if (ho >= 0 && ho < Ho && wo >= 0 && wo < Wo) {
        long long base = ((long long)(b * C + c) * H + ho * 2) * W + wo * 2;
        float v[4] = {0.f, 0.f, 0.f, 0.f};
#pragma unroll
        for (int p = 0; p < NP; p++) {
            const float* ip = in + p * sz + base;
            v[0] += ip[0];
            v[1] += ip[1];
            v[2] += ip[W];
            v[3] += ip[W + 1];
        }
        m = fmaxf(fmaxf(fmaxf(v[0], v[1]), fmaxf(v[2], v[3])), 0.0f);
    }
    float cf[9];
    eval9(m, cf);
    long long idxH = ((long long)(b * C + c) * HPd + hp_) * WPH + (wp_ >> 1);
    store_phi_par(phi, npixh, wp_ & 1, idxH, cf);
}

template <int NP>
__global__ void reduce_relu(const float* __restrict__ in, float* __restrict__ out,
                            int n) {
    int idx = blockIdx.x * blockDim.x + threadIdx.x;
    if (idx >= n) return;
    float s = 0.0f;
#pragma unroll
    for (int p = 0; p < NP; p++) s += in[(long long)p * n + idx];
    out[idx] = fmaxf(s, 0.0f);
}

// ---------------------------------------------------------------------------
// Head: mean(7x7) -> KAN linear 64 -> 200.  8 blocks x 25 outputs.
// ---------------------------------------------------------------------------
__global__ void classifier_kernel(const float* __restrict__ act,
                                  const float* __restrict__ wp,
                                  float* __restrict__ out) {
    __shared__ float mean[512];
    __shared__ float cs[512 * 5];
    __shared__ int   cr[512 * 4];
    int tid = threadIdx.x;
    int ot  = blockIdx.x;

    for (int e = tid; e < 512; e += 256) {
        const float* p = act + e * 49;
        float s = 0.0f;
#pragma unroll
        for (int i = 0; i < 49; i++) s += p[i];
        mean[e] = s * (1.0f / 49.0f);
    }
    __syncthreads();
    for (int e = tid; e < 512; e += 256) {
        float c0, w4[4];
        int   rw[4];
        eval5(mean[e], c0, w4, rw);
        cs[e * 5 + 0] = c0;
#pragma unroll
        for (int t = 0; t < 4; t++) {
            cs[e * 5 + 1 + t] = w4[t];
            cr[e * 4 + t]     = rw[t];
        }
    }
    __syncthreads();
    if (tid < 200) {
        int b = tid / 25;
        int o = ot * 25 + tid % 25;
        float acc = 0.0f;
#pragma unroll 4
        for (int i = 0; i < 64; i++) {
            int e = b * 64 + i;
            const float* cp = &cs[e * 5];
            const int*   rp = &cr[e * 4];
            const float* wr = wp + i * 9 * 200 + o;
            acc = fmaf(cp[0], wr[0], acc);
            acc = fmaf(cp[1], wr[rp[0] * 200], acc);
            acc = fmaf(cp[2], wr[rp[1] * 200], acc);
            acc = fmaf(cp[3], wr[rp[2] * 200], acc);
            acc = fmaf(cp[4], wr[rp[3] * 200], acc);
        }
        out[b * 200 + o] = acc;
    }
}

// ---------------------------------------------------------------------------
// Host launcher
// ---------------------------------------------------------------------------
static void* sym_addr(const void* symbol) {
    void* p = nullptr;
    cudaGetSymbolAddress(&p, symbol);
    return p;
}

extern "C" void kernel_launch(void* const* d_in, const int* in_sizes, int n_in,
                              void* d_out, int out_size) {
    const float* x   = (const float*)d_in[0];
    const float* bw0 = (const float*)d_in[1];
    const float* sw0 = (const float*)d_in[2];
    const float* sc0 = (const float*)d_in[3];
    const float* bw1 = (const float*)d_in[4];
    const float* sw1 = (const float*)d_in[5];
    const float* sc1 = (const float*)d_in[6];
    const float* bw2 = (const float*)d_in[7];
    const float* sw2 = (const float*)d_in[8];
    const float* sc2 = (const float*)d_in[9];
    const float* bwc = (const float*)d_in[10];
    const float* swc = (const float*)d_in[11];
    const float* scc = (const float*)d_in[12];
    float* out = (float*)d_out;

    float*  wp0   = (float*)sym_addr(g_wp0);
    float*  wp1   = (float*)sym_addr(g_wp1);
    float*  wp2   = (float*)sym_addr(g_wp2);
    float*  wpc   = (float*)sym_addr(g_wpc);
    float2* phi0  = (float2*)sym_addr(g_phi0);
    float*  part0 = (float*)sym_addr(g_part0);
    float2* phi1  = (float2*)sym_addr(g_phi1);
    float*  part1 = (float*)sym_addr(g_part1);
    float2* phi2  = (float2*)sym_addr(g_phi2);
    float*  part2 = (float*)sym_addr(g_part2);
    float*  a2    = (float*)sym_addr(g_a2);

    {
        int total = N0P + N1P + N2P + NCP;
        pack_all<<<(total + 255) / 256, 256>>>(bw0, sw0, sc0, bw1, sw1, sc1,
                                               bw2, sw2, sc2, bwc, swc, scc,
                                               wp0, wp1, wp2, wpc);
    }

    // ---- L0: parity phi -> conv (196x3, PX=4, CSL=1 ch/slice) -> pool+phi ----
    {
        int ncell0 = 8 * 3 * HP0 * (2 * WPH0);
        phi_eval_pad<<<(ncell0 + 255) / 256, 256>>>(x, phi0, 8, 3, 224, 224, 3,
                                                    WPH0, NPIXH0);
        auto k = kan_conv_g<3, 7, 16, 16, 4, 128, 1>;
        dim3 grid(196, 3);
        k<<<grid, 128>>>(phi0, wp0, part0, 8, HP0, WPH0, 112, 112);
        int ncell1 = 8 * 16 * HP1 * (2 * WPH1);
        maxpool_sum_phi_pad<3><<<(ncell1 + 255) / 256, 256>>>(part0, phi1,
                                                              8, 16, 112, 112, 1,
                                                              WPH1, NPIXH1);
    }
    // ---- L1: 16 slices (1 ch) x 2 o-tiles = 416 blocks -> pool+phi ----
    {
        auto k = kan_conv_g<16, 3, 32, 16, 4, 128, 1>;
        dim3 grid(13, 32);
        k<<<grid, 128>>>(phi1, wp1, part1, 8, HP1, WPH1, 28, 28);
        int ncell2 = 8 * 32 * HP2 * (2 * WPH2);
        maxpool_sum_phi_pad<16><<<(ncell2 + 255) / 256, 256>>>(part1, phi2,
                                                               8, 32, 28, 28, 1,
                                                               WPH2, NPIXH2);
    }
    // ---- L2: 32 slices (1 ch) x 4 o-tiles = 512 blocks -> reduce_relu ----
    {
        auto k = kan_conv_g<32, 3, 64, 16, 1, 128, 1>;
        dim3 grid(4, 128);
        k<<<grid, 128>>>(phi2, wp2, part2, 8, HP2, WPH2, 7, 7);
        reduce_relu<32><<<(8 * 64 * 7 * 7 + 255) / 256, 256>>>(part2, a2, 8 * 64 * 7 * 7);
    }
    classifier_kernel<<<8, 256>>>(a2, wpc, out);

    (void)in_sizes; (void)n_in; (void)out_size;
}

// round 14
// speedup vs baseline: 1.0476x; 1.0476x over previous
#include <cuda_runtime.h>
#include <math.h>

// ---------------------------------------------------------------------------
// KANConvNet round 13: R11 baseline (padded phi, no bounds checks, uniform
// incremental tap offset) with phi repacked as float4+float4+float planes:
// 3 LDGs per tap instead of 5. Everything else identical to the 186.4us R11.
// ---------------------------------------------------------------------------

// L0 input (x): 8x3x224x224, pad 3 -> 230x230
#define HP0 230
#define NPAD0 (8 * 3 * HP0 * HP0)
// L1 input (pooled 56x56), pad 1 -> 58x58
#define HP1 58
#define NPAD1 (8 * 16 * HP1 * HP1)
// L2 input (pooled 14x14), pad 1 -> 16x16
#define HP2 16
#define NPAD2 (8 * 32 * HP2 * HP2)

__device__ float g_wp0[147 * 9 * 16];
__device__ float g_wp1[144 * 9 * 32];
__device__ float g_wp2[288 * 9 * 64];
__device__ float g_wpc[64  * 9 * 200];

__device__ float4 g_phi0a[NPAD0];
__device__ float4 g_phi0b[NPAD0];
__device__ float  g_phi0c[NPAD0];
__device__ float  g_part0[3 * 8 * 16 * 112 * 112];
__device__ float4 g_phi1a[NPAD1];
__device__ float4 g_phi1b[NPAD1];
__device__ float  g_phi1c[NPAD1];
__device__ float  g_part1[12 * 8 * 32 * 28 * 28];
__device__ float4 g_phi2a[NPAD2];
__device__ float4 g_phi2b[NPAD2];
__device__ float  g_phi2c[NPAD2];
__device__ float  g_part2[36 * 8 * 64 * 7 * 7];
__device__ float  g_a2[8 * 64 * 7 * 7];

#define N0P (147 * 9 * 16)
#define N1P (144 * 9 * 32)
#define N2P (288 * 9 * 64)
#define NCP (64  * 9 * 200)

// ---------------- packed f32x2 helpers ----------------
__device__ __forceinline__ long long pk2(float a) {
    long long r;
    asm("mov.b64 %0, {%1, %1};" : "=l"(r) : "f"(a));
    return r;
}
__device__ __forceinline__ long long ffma2(long long a, long long b, long long c) {
    long long d;
    asm("fma.rn.f32x2 %0, %1, %2, %3;" : "=l"(d) : "l"(a), "l"(b), "l"(c));
    return d;
}
__device__ __forceinline__ float2 upk2(long long a) {
    float x, y;
    asm("mov.b64 {%0, %1}, %2;" : "=f"(x), "=f"(y) : "l"(a));
    return make_float2(x, y);
}

// ---------------- dense 9-coefficient evaluation ----------------
__device__ __forceinline__ void eval9(float x, float* c) {
    float sig = 1.0f / (1.0f + __expf(-x));
    c[0] = x * sig;
    float t  = fmaf(x, 2.5f, 5.5f);          // (x + 2.2) / 0.4
    float mf = floorf(t);
    bool inr = (mf >= 0.0f) && (mf <= 10.0f);
    mf = fminf(fmaxf(mf, 0.0f), 10.0f);
    float u  = t - mf;
    float u2 = u * u;
    float u3 = u2 * u;
    float om = 1.0f - u;
    const float s6 = 1.0f / 6.0f;
    float w0 = s6 * om * om * om;
    float w1 = s6 * fmaf(3.0f, u3, fmaf(-6.0f, u2, 4.0f));
    float w2 = s6 * fmaf(-3.0f, u3, fmaf(3.0f, u2, fmaf(3.0f, u, 1.0f)));
    float w3 = s6 * u3;
    int m = (int)mf;
#pragma unroll
    for (int r = 1; r < 9; r++) {
        int tt = (r - 1) - (m - 3);
        float cv = 0.0f;
        cv = (tt == 0) ? w0 : cv;
        cv = (tt == 1) ? w1 : cv;
        cv = (tt == 2) ? w2 : cv;
        cv = (tt == 3) ? w3 : cv;
        c[r] = inr ? cv : 0.0f;
    }
}

// eval5 (sparse) for the classifier head
__device__ __forceinline__ void eval5(float x, float& c0, float* w, int* r) {
    float sig = 1.0f / (1.0f + __expf(-x));
    c0 = x * sig;
    float t  = fmaf(x, 2.5f, 5.5f);
    float mf = floorf(t);
    bool inr = (mf >= 0.0f) && (mf <= 10.0f);
    mf = fminf(fmaxf(mf, 0.0f), 10.0f);
    float u  = t - mf;
    float u2 = u * u;
    float u3 = u2 * u;
    float om = 1.0f - u;
    const float s6 = 1.0f / 6.0f;
    float a0 = s6 * om * om * om;
    float a1 = s6 * fmaf(3.0f, u3, fmaf(-6.0f, u2, 4.0f));
    float a2 = s6 * fmaf(-3.0f, u3, fmaf(3.0f, u2, fmaf(3.0f, u, 1.0f)));
    float a3 = s6 * u3;
    int m = (int)mf;
    w[0] = (inr && m >= 3)            ? a0 : 0.0f;
    w[1] = (inr && m >= 2 && m <= 9)  ? a1 : 0.0f;
    w[2] = (inr && m >= 1 && m <= 8)  ? a2 : 0.0f;
    w[3] = (inr && m <= 7)            ? a3 : 0.0f;
#pragma unroll
    for (int t4 = 0; t4 < 4; t4++) {
        int j = m - 3 + t4;
        j = j < 0 ? 0 : (j > 7 ? 7 : j);
        r[t4] = 1 + j;
    }
}

__device__ __forceinline__ void store_phi_abc(float4* pa, float4* pb, float* pc,
                                              long long i, const float* c) {
    pa[i] = make_float4(c[0], c[1], c[2], c[3]);
    pb[i] = make_float4(c[4], c[5], c[6], c[7]);
    pc[i] = c[8];
}

// ---------------- phi precompute into PADDED layout (layer-0 input) --------
__global__ void phi_eval_pad(const float* __restrict__ x,
                             float4* __restrict__ pa, float4* __restrict__ pb,
                             float* __restrict__ pc,
                             int B, int C, int H, int W, int P, int npad) {
    int i = blockIdx.x * blockDim.x + threadIdx.x;
    if (i >= npad) return;
    int WP = W + 2 * P, HPd = H + 2 * P;
    int wp_ = i % WP;
    int t   = i / WP;
    int hp_ = t % HPd;
    t /= HPd;
    int c = t % C;
    int b = t / C;
    int hin = hp_ - P, win = wp_ - P;
    float xv = 0.0f;
    if (hin >= 0 && hin < H && win >= 0 && win < W)
        xv = x[((b * C + c) * H + hin) * W + win];
    float cf[9];
    eval9(xv, cf);
    store_phi_abc(pa, pb, pc, i, cf);
}

// ---------------- merged weight packing ----------------
__device__ __forceinline__ void pack_one(int idx,
                                         const float* __restrict__ bw,
                                         const float* __restrict__ sw,
                                         const float* __restrict__ sc,
                                         float* __restrict__ wp,
                                         int OUT, int IN) {
    int i   = idx / (9 * OUT);
    int rem = idx - i * 9 * OUT;
    int r   = rem / OUT;
    int o   = rem - r * OUT;
    int oi  = o * IN + i;
    float v = (r == 0) ? bw[oi] : sw[oi * 8 + (r - 1)] * sc[oi];
    wp[idx] = v;
}

__global__ void pack_all(const float* bw0, const float* sw0, const float* sc0,
                         const float* bw1, const float* sw1, const float* sc1,
                         const float* bw2, const float* sw2, const float* sc2,
                         const float* bwc, const float* swc, const float* scc,
                         float* wp0, float* wp1, float* wp2, float* wpc) {
    int idx = blockIdx.x * blockDim.x + threadIdx.x;
    if (idx < N0P) { pack_one(idx, bw0, sw0, sc0, wp0, 16, 147); return; }
    idx -= N0P;
    if (idx < N1P) { pack_one(idx, bw1, sw1, sc1, wp1, 32, 144); return; }
    idx -= N1P;
    if (idx < N2P) { pack_one(idx, bw2, sw2, sc2, wp2, 64, 288); return; }
    idx -= N2P;
    if (idx < NCP) { pack_one(idx, bwc, swc, scc, wpc, 200, 64); }
}

// ---------------------------------------------------------------------------
// Dense gather-GEMM conv over PADDED phi (a/b/c planes): no bounds checks.
// ---------------------------------------------------------------------------
template <int CIN, int K, int S, int OUT, int OT, int PX, int T, int FSL>
__global__ void __launch_bounds__(T, 3)
kan_conv_g(const float4* __restrict__ pa, const float4* __restrict__ pb,
           const float* __restrict__ pc,
           const float* __restrict__ wp,    // [F][9][OUT]
           float* __restrict__ out,
           int B, int HPd, int WPd, int Ho, int Wo) {
    __shared__ float swm[FSL * 9 * OT];
    const int NOT = OUT / OT;
    const int sl  = blockIdx.y / NOT;
    const int ot  = blockIdx.y - sl * NOT;

    for (int idx = threadIdx.x; idx < FSL * 9 * OT; idx += T) {
        int f   = idx / (9 * OT);
        int rem = idx - f * 9 * OT;
        int r   = rem / OT;
        int o   = rem - r * OT;
        swm[idx] = wp[((sl * FSL + f) * 9 + r) * OUT + ot * OT + o];
    }
    __syncthreads();

    const int N = B * Ho * Wo;
    int  off[PX];
    bool pv[PX];
#pragma unroll
    for (int p = 0; p < PX; p++) {
        int gp = blockIdx.x * T * PX + p * T + threadIdx.x;
        pv[p]  = gp < N;
        int g  = pv[p] ? gp : 0;
        int b  = g / (Ho * Wo);
        int rr = g - b * Ho * Wo;
        int ho = rr / Wo;
        int wo = rr - ho * Wo;
        off[p] = b * CIN * HPd * WPd + (ho * S) * WPd + wo * S;
    }

    long long acc[PX][OT / 2];
#pragma unroll
    for (int p = 0; p < PX; p++)
#pragma unroll
        for (int k = 0; k < OT / 2; k++) acc[p][k] = 0LL;

    // block-uniform incremental tap offset
    int f0 = sl * FSL;
    int c  = f0 / (K * K);
    int r0 = f0 - c * K * K;
    int kh = r0 / K;
    int kw = r0 - kh * K;
    int uofs = (c * HPd + kh) * WPd + kw;

#pragma unroll 1
    for (int fl = 0; fl < FSL; fl++) {
        float4 crA[PX];
        float4 crB[PX];
        float  crC[PX];
#pragma unroll
        for (int p = 0; p < PX; p++) {
            int idx = off[p] + uofs;
            crA[p] = __ldg(pa + idx);
            crB[p] = __ldg(pb + idx);
            crC[p] = __ldg(pc + idx);
        }

        const float* wr = swm + fl * 9 * OT;
#pragma unroll
        for (int r = 0; r < 9; r++) {
            const ulonglong2* wv = (const ulonglong2*)(wr + r * OT);
#pragma unroll
            for (int p = 0; p < PX; p++) {
                float cf;
                if      (r == 0) cf = crA[p].x;
                else if (r == 1) cf = crA[p].y;
                else if (r == 2) cf = crA[p].z;
                else if (r == 3) cf = crA[p].w;
                else if (r == 4) cf = crB[p].x;
                else if (r == 5) cf = crB[p].y;
                else if (r == 6) cf = crB[p].z;
                else if (r == 7) cf = crB[p].w;
                else             cf = crC[p];
                long long cp = pk2(cf);
#pragma unroll
                for (int q = 0; q < OT / 4; q++) {
                    ulonglong2 a = wv[q];
                    acc[p][2 * q]     = ffma2(cp, (long long)a.x, acc[p][2 * q]);
                    acc[p][2 * q + 1] = ffma2(cp, (long long)a.y, acc[p][2 * q + 1]);
                }
            }
        }

        kw++; uofs++;
        if (kw == K) {
            kw = 0; kh++; uofs += WPd - K;
            if (kh == K) { kh = 0; c++; uofs += (HPd - K) * WPd; }
        }
    }

    long long HW = (long long)Ho * Wo;
    float* ob = out + (long long)sl * B * OUT * HW;
#pragma unroll
    for (int p = 0; p < PX; p++) {
        if (!pv[p]) continue;
        int gp = blockIdx.x * T * PX + p * T + threadIdx.x;
        int b  = gp / (Ho * Wo);
        int rr = gp - b * Ho * Wo;
        float* op = ob + (long long)(b * OUT + ot * OT) * HW + rr;
#pragma unroll
        for (int k = 0; k < OT / 2; k++) {
            float2 v = upk2(acc[p][k]);
            op[(2 * k) * HW]     = v.x;
            op[(2 * k + 1) * HW] = v.y;
        }
    }
}

// ---------------------------------------------------------------------------
// sum NP partials -> relu -> 2x2 max pool -> phi into PADDED next-layer layout
// ---------------------------------------------------------------------------
template <int NP>
__global__ void maxpool_sum_phi_pad(const float* __restrict__ in,
                                    float4* __restrict__ pa,
                                    float4* __restrict__ pb,
                                    float* __restrict__ pc,
                                    int B, int C, int H, int W,   // pre-pool dims
                                    int P, int npad) {
    int Ho = H / 2, Wo = W / 2;
    int WP = Wo + 2 * P, HPd = Ho + 2 * P;
    long long sz = (long long)B * C * H * W;
    int i = blockIdx.x * blockDim.x + threadIdx.x;
    if (i >= npad) return;
    int wp_ = i % WP;
    int t   = i / WP;
    int hp_ = t % HPd;
    t /= HPd;
    int c = t % C;
    int b = t / C;
    int ho = hp_ - P, wo = wp_ - P;
    float m = 0.0f;
    if (ho >= 0 && ho < Ho && wo >= 0 && wo < Wo) {
        long long base = ((long long)(b * C + c) * H + ho * 2) * W + wo * 2;
        float v[4] = {0.f, 0.f, 0.f, 0.f};
#pragma unroll
        for (int p = 0; p < NP; p++) {
            const float* ip = in + p * sz + base;
            v[0] += ip[0];
            v[1] += ip[1];
            v[2] += ip[W];
            v[3] += ip[W + 1];
        }
        m = fmaxf(fmaxf(fmaxf(v[0], v[1]), fmaxf(v[2], v[3])), 0.0f);
    }
    float cf[9];
    eval9(m, cf);
    store_phi_abc(pa, pb, pc, i, cf);
}

template <int NP>
__global__ void reduce_relu(const float* __restrict__ in, float* __restrict__ out,
                            int n) {
    int idx = blockIdx.x * blockDim.x + threadIdx.x;
    if (idx >= n) return;
    float s = 0.0f;
#pragma unroll
    for (int p = 0; p < NP; p++) s += in[(long long)p * n + idx];
    out[idx] = fmaxf(s, 0.0f);
}

// ---------------------------------------------------------------------------
// Head: mean(7x7) -> KAN linear 64 -> 200.  8 blocks x 25 outputs.
// ---------------------------------------------------------------------------
__global__ void classifier_kernel(const float* __restrict__ act,
                                  const float* __restrict__ wp,
                                  float* __restrict__ out) {
    __shared__ float mean[512];
    __shared__ float cs[512 * 5];
    __shared__ int   cr[512 * 4];
    int tid = threadIdx.x;
    int ot  = blockIdx.x;

    for (int e = tid; e < 512; e += 256) {
        const float* p = act + e * 49;
        float s = 0.0f;
#pragma unroll
        for (int i = 0; i < 49; i++) s += p[i];
        mean[e] = s * (1.0f / 49.0f);
    }
    __syncthreads();
    for (int e = tid; e < 512; e += 256) {
        float c0, w4[4];
        int   rw[4];
        eval5(mean[e], c0, w4, rw);
        cs[e * 5 + 0] = c0;
#pragma unroll
        for (int t = 0; t < 4; t++) {
            cs[e * 5 + 1 + t] = w4[t];
            cr[e * 4 + t]     = rw[t];
        }
    }
    __syncthreads();
    if (tid < 200) {
        int b = tid / 25;
        int o = ot * 25 + tid % 25;
        float acc = 0.0f;
#pragma unroll 4
        for (int i = 0; i < 64; i++) {
            int e = b * 64 + i;
            const float* cp = &cs[e * 5];
            const int*   rp = &cr[e * 4];
            const float* wr = wp + i * 9 * 200 + o;
            acc = fmaf(cp[0], wr[0], acc);
            acc = fmaf(cp[1], wr[rp[0] * 200], acc);
            acc = fmaf(cp[2], wr[rp[1] * 200], acc);
            acc = fmaf(cp[3], wr[rp[2] * 200], acc);
            acc = fmaf(cp[4], wr[rp[3] * 200], acc);
        }
        out[b * 200 + o] = acc;
    }
}

// ---------------------------------------------------------------------------
// Host launcher
// ---------------------------------------------------------------------------
static void* sym_addr(const void* symbol) {
    void* p = nullptr;
    cudaGetSymbolAddress(&p, symbol);
    return p;
}

extern "C" void kernel_launch(void* const* d_in, const int* in_sizes, int n_in,
                              void* d_out, int out_size) {
    const float* x   = (const float*)d_in[0];
    const float* bw0 = (const float*)d_in[1];
    const float* sw0 = (const float*)d_in[2];
    const float* sc0 = (const float*)d_in[3];
    const float* bw1 = (const float*)d_in[4];
    const float* sw1 = (const float*)d_in[5];
    const float* sc1 = (const float*)d_in[6];
    const float* bw2 = (const float*)d_in[7];
    const float* sw2 = (const float*)d_in[8];
    const float* sc2 = (const float*)d_in[9];
    const float* bwc = (const float*)d_in[10];
    const float* swc = (const float*)d_in[11];
    const float* scc = (const float*)d_in[12];
    float* out = (float*)d_out;

    float*  wp0   = (float*)sym_addr(g_wp0);
    float*  wp1   = (float*)sym_addr(g_wp1);
    float*  wp2   = (float*)sym_addr(g_wp2);
    float*  wpc   = (float*)sym_addr(g_wpc);
    float4* p0a   = (float4*)sym_addr(g_phi0a);
    float4* p0b   = (float4*)sym_addr(g_phi0b);
    float*  p0c   = (float*)sym_addr(g_phi0c);
    float*  part0 = (float*)sym_addr(g_part0);
    float4* p1a   = (float4*)sym_addr(g_phi1a);
    float4* p1b   = (float4*)sym_addr(g_phi1b);
    float*  p1c   = (float*)sym_addr(g_phi1c);
    float*  part1 = (float*)sym_addr(g_part1);
    float4* p2a   = (float4*)sym_addr(g_phi2a);
    float4* p2b   = (float4*)sym_addr(g_phi2b);
    float*  p2c   = (float*)sym_addr(g_phi2c);
    float*  part2 = (float*)sym_addr(g_part2);
    float*  a2    = (float*)sym_addr(g_a2);

    {
        int total = N0P + N1P + N2P + NCP;
        pack_all<<<(total + 255) / 256, 256>>>(bw0, sw0, sc0, bw1, sw1, sc1,
                                               bw2, sw2, sc2, bwc, swc, scc,
                                               wp0, wp1, wp2, wpc);
    }

    // ---- L0: padded phi -> conv (196x3 blocks, PX=4) -> pool+phi(padded) ----
    phi_eval_pad<<<(NPAD0 + 255) / 256, 256>>>(x, p0a, p0b, p0c,
                                               8, 3, 224, 224, 3, NPAD0);
    {
        auto k = kan_conv_g<3, 7, 2, 16, 16, 4, 128, 49>;
        dim3 grid(196, 3);
        k<<<grid, 128>>>(p0a, p0b, p0c, wp0, part0, 8, HP0, HP0, 112, 112);
        maxpool_sum_phi_pad<3><<<(NPAD1 + 255) / 256, 256>>>(part0, p1a, p1b, p1c,
                                                             8, 16, 112, 112, 1, NPAD1);
    }
    // ---- L1: 12 K-slices x 2 o-tiles -> pool+phi(padded) ----
    {
        auto k = kan_conv_g<16, 3, 2, 32, 16, 4, 128, 12>;
        dim3 grid(13, 24);
        k<<<grid, 128>>>(p1a, p1b, p1c, wp1, part1, 8, HP1, HP1, 28, 28);
        maxpool_sum_phi_pad<12><<<(NPAD2 + 255) / 256, 256>>>(part1, p2a, p2b, p2c,
                                                              8, 32, 28, 28, 1, NPAD2);
    }
    // ---- L2: 36 K-slices x 4 o-tiles -> reduce_relu ----
    {
        auto k = kan_conv_g<32, 3, 2, 64, 16, 1, 128, 8>;
        dim3 grid(4, 144);
        k<<<grid, 128>>>(p2a, p2b, p2c, wp2, part2, 8, HP2, HP2, 7, 7);
        reduce_relu<36><<<(8 * 64 * 7 * 7 + 255) / 256, 256>>>(part2, a2, 8 * 64 * 7 * 7);
    }
    classifier_kernel<<<8, 256>>>(a2, wpc, out);

    (void)in_sizes; (void)n_in; (void)out_size;
}